// round 9
// baseline (speedup 1.0000x reference)
#include <cuda_runtime.h>
#include <cstddef>

typedef unsigned long long ull;

#define NTHREADS 256
#define TROWS 64

// ======== transposed-weight global scratch: Wt[j][k] per layer ========
__device__ __align__(16) float g_wt[65536];
__constant__ int c_pre[10]  = {0,4096,8192,12288,18688,25088,31488,52224,61440,65536};
__constant__ int c_nin[9]   = {64,64,64,80,80,80,144,144,64};
__constant__ int c_nout[9]  = {64,64,64,80,80,80,144,64,64};

__global__ void prep_kernel(const float* w0,const float* w1,const float* w2,
                            const float* w3,const float* w4,const float* w5,
                            const float* w6,const float* w7,const float* w8)
{
    const float* W[9] = {w0,w1,w2,w3,w4,w5,w6,w7,w8};
    int i = blockIdx.x * blockDim.x + threadIdx.x;
    if (i >= 65536) return;
    int s = 0;
    while (i >= c_pre[s + 1]) s++;
    int l = i - c_pre[s];
    int nin = c_nin[s], nout = c_nout[s];
    int j = l / nin, k = l - j * nin;
    g_wt[i] = W[s][k * nout + j];
}

// ======== packed fp32x2 + cp.async helpers ========
__device__ __forceinline__ ull ffma2(ull a, ull b, ull c) {
    ull d; asm("fma.rn.f32x2 %0, %1, %2, %3;" : "=l"(d) : "l"(a), "l"(b), "l"(c)); return d;
}
__device__ __forceinline__ float2 u2f(ull a) {
    float2 f; asm("mov.b64 {%0, %1}, %2;" : "=f"(f.x), "=f"(f.y) : "l"(a)); return f;
}
__device__ __forceinline__ float lrelu(float v) { return v > 0.0f ? v : 0.01f * v; }
__device__ __forceinline__ void cpa16(float* dst, const float* src) {
    unsigned sa = (unsigned)__cvta_generic_to_shared(dst);
    asm volatile("cp.async.cg.shared.global [%0], [%1], 16;" :: "r"(sa), "l"(src));
}
#define CPA_COMMIT() asm volatile("cp.async.commit_group;" ::: "memory")
#define CPA_WAIT0()  asm volatile("cp.async.wait_group 0;"  ::: "memory")

// ======== epilogue chunk maps ========
__constant__ int c_kind[31] = {0,0,0,0,0,0,0,0,0,0,0,0,1,1,1,1,0,0,0,1,0,0,0,0,0,1,1,1,1,1,1};
__constant__ int c_A[31]    = {320,152,304,304,304,304,304,152,152,152,152,152,
                               40,41,42,43, 152,208,416, 39, 208,152,416,360,152,
                               44,45,46,47,48,49};
__constant__ int c_B[31]    = {18,20,22,23,24,25,26,27,28,29,30,31,
                               0,2,3,5, 35,36,37, 1, 32,33,34,19,38,
                               4,4,4,4,4,4};
// blob: suit@0(40) rank@40(112) pos@152(56) action@208(96) active@304(16)
//       street@320(40) numpl@360(56) blind@416(16)

// ======== shared layout (floats) ========
#define OFF_BLOB 0                   // 432
#define OFF_SW   432                 // 48
#define OFF_SB   480                 // 48
#define OFF_BIAS 528                 // 704 (ends 1232)
#define OFF_A    1232                // 64*84 = 5376 (stride 84)
#define OFF_B    6608                // 64*84 = 5376
#define OFF_C    11984               // 64*148 = 9472 (stride 148)
#define OFF_W    21456               // 2 slots * 3584
#define SLOTF    3584
#define SMEM_FLOATS 28624
#define SMEM_BYTES  (SMEM_FLOATS * 4)  // 114496 -> 2 CTAs/SM
// D (144-wide, stride 148) overlays A+B (10752 >= 9472)

// ======== weight-chunk stage (cp.async, commit; no wait) ========
template<int NJ_, int NIN_, int KC_>
__device__ __forceinline__ void stage_chunk(float* __restrict__ dst,
                                            const float* __restrict__ src)
{
    constexpr int PER = KC_ / 4;
    constexpr int WS  = KC_ + 4;
    const int t = threadIdx.x;
    for (int i = t; i < NJ_ * PER; i += NTHREADS) {
        int j = i / PER, k4 = (i - j * PER) << 2;
        cpa16(dst + j * WS + k4, src + j * NIN_ + k4);
    }
    CPA_COMMIT();
}

// ======== dense (sub-)layer: 2 rows/lane, k-pair FFMA2, pipelined weights ========
// PRECONDITION: chunk 0 already staged into slot S0 and visible (barrier done).
// Prefetches next-layer chunk0 (NNJ>0) during last chunk's compute.
template<int NIN, int SIN, int NJ, int SOUT, int JOFF, int KC, bool ACT, int S0,
         int NNJ, int NNIN, int NKC>
__device__ __forceinline__ void layer4(const float* __restrict__ Xs, float* __restrict__ Ys,
                                       const float* __restrict__ Wtg,
                                       const float* __restrict__ bsm,
                                       float* __restrict__ Wslots,
                                       const float* __restrict__ nextWtg)
{
    const int t = threadIdx.x, L = t & 31, wid = t >> 5;
    constexpr int TILEJ = NJ / 8;
    constexpr int WS  = KC + 4;
    constexpr int NCH = NIN / KC;
    const int j0 = wid * TILEJ;

    ull acc[TILEJ][2];
    #pragma unroll
    for (int j = 0; j < TILEJ; j++) { acc[j][0] = 0ull; acc[j][1] = 0ull; }

    const float* x0 = Xs + L * SIN;
    const float* x1 = Xs + (L + 32) * SIN;

    #pragma unroll
    for (int c = 0; c < NCH; c++) {
        if (c + 1 < NCH) {
            stage_chunk<NJ, NIN, KC>(Wslots + ((S0 + c + 1) & 1) * SLOTF,
                                     Wtg + (c + 1) * KC);
        } else if (NNJ > 0) {
            stage_chunk<NNJ, NNIN, NKC>(Wslots + ((S0 + NCH) & 1) * SLOTF, nextWtg);
        }
        // ---- compute chunk c ----
        {
            const float* Wt = Wslots + ((S0 + c) & 1) * SLOTF + j0 * WS;
            const float* xk0 = x0 + c * KC;
            const float* xk1 = x1 + c * KC;
            #pragma unroll 4
            for (int k = 0; k < KC; k += 4) {
                ulonglong2 xa = *reinterpret_cast<const ulonglong2*>(xk0 + k);
                ulonglong2 xb = *reinterpret_cast<const ulonglong2*>(xk1 + k);
                const float* wr = Wt + k;
                #pragma unroll
                for (int j = 0; j < TILEJ; j++) {
                    ulonglong2 wv = *reinterpret_cast<const ulonglong2*>(wr + j * WS);
                    acc[j][0] = ffma2(xa.x, wv.x, acc[j][0]);
                    acc[j][0] = ffma2(xa.y, wv.y, acc[j][0]);
                    acc[j][1] = ffma2(xb.x, wv.x, acc[j][1]);
                    acc[j][1] = ffma2(xb.y, wv.y, acc[j][1]);
                }
            }
        }
        if (c + 1 < NCH) { CPA_WAIT0(); __syncthreads(); }
    }

    // epilogue: horizontal add + bias (+act)
    #pragma unroll
    for (int j = 0; j < TILEJ; j += 2) {
        float b0 = bsm[j0 + j], b1 = bsm[j0 + j + 1];
        #pragma unroll
        for (int r = 0; r < 2; r++) {
            float2 s0 = u2f(acc[j][r]);
            float2 s1 = u2f(acc[j + 1][r]);
            float v0 = s0.x + s0.y + b0;
            float v1 = s1.x + s1.y + b1;
            if (ACT) { v0 = lrelu(v0); v1 = lrelu(v1); }
            *reinterpret_cast<float2*>(Ys + (L + 32 * r) * SOUT + JOFF + j0 + j) =
                make_float2(v0, v1);
        }
    }
    CPA_WAIT0();      // next-layer chunk0 landed (no-op when none)
    __syncthreads();  // acts visible + weight slot handoff
}

// final 64->64 layer (chunk0 pre-staged into slot S0F=1): writes out cols [0,64)
__device__ __forceinline__ void layer_final(const float* __restrict__ Xs,
                                            const float* __restrict__ Wtg,
                                            const float* __restrict__ bsm,
                                            float* __restrict__ Wslots,
                                            float* __restrict__ out, size_t g0)
{
    const int t = threadIdx.x, L = t & 31, wid = t >> 5;
    constexpr int KC = 32, WS = 36, NCH = 2, S0 = 1;
    const int j0 = wid * 8;

    ull acc[8][2];
    #pragma unroll
    for (int j = 0; j < 8; j++) { acc[j][0] = 0ull; acc[j][1] = 0ull; }

    const float* x0 = Xs + L * 148;
    const float* x1 = Xs + (L + 32) * 148;

    #pragma unroll
    for (int c = 0; c < NCH; c++) {
        if (c + 1 < NCH)
            stage_chunk<64, 64, 32>(Wslots + ((S0 + c + 1) & 1) * SLOTF, Wtg + (c + 1) * KC);
        {
            const float* Wt = Wslots + ((S0 + c) & 1) * SLOTF + j0 * WS;
            const float* xk0 = x0 + c * KC;
            const float* xk1 = x1 + c * KC;
            #pragma unroll 4
            for (int k = 0; k < KC; k += 4) {
                ulonglong2 xa = *reinterpret_cast<const ulonglong2*>(xk0 + k);
                ulonglong2 xb = *reinterpret_cast<const ulonglong2*>(xk1 + k);
                const float* wr = Wt + k;
                #pragma unroll
                for (int j = 0; j < 8; j++) {
                    ulonglong2 wv = *reinterpret_cast<const ulonglong2*>(wr + j * WS);
                    acc[j][0] = ffma2(xa.x, wv.x, acc[j][0]);
                    acc[j][0] = ffma2(xa.y, wv.y, acc[j][0]);
                    acc[j][1] = ffma2(xb.x, wv.x, acc[j][1]);
                    acc[j][1] = ffma2(xb.y, wv.y, acc[j][1]);
                }
            }
        }
        if (c + 1 < NCH) { CPA_WAIT0(); __syncthreads(); }
    }

    #pragma unroll
    for (int r = 0; r < 2; r++) {
        float v[8];
        #pragma unroll
        for (int j = 0; j < 8; j++) {
            float2 s = u2f(acc[j][r]);
            v[j] = s.x + s.y + bsm[j0 + j];
        }
        float* op = out + (g0 + L + 32 * r) * 312 + j0;
        *reinterpret_cast<float4*>(op)     = make_float4(v[0], v[1], v[2], v[3]);
        *reinterpret_cast<float4*>(op + 4) = make_float4(v[4], v[5], v[6], v[7]);
    }
}

__global__ void __launch_bounds__(NTHREADS, 2)
preproc_kernel(const float* __restrict__ state,
               const float* __restrict__ suit_emb, const float* __restrict__ rank_emb,
               const float* __restrict__ hb1, const float* __restrict__ hb2,
               const float* __restrict__ hb3, const float* __restrict__ bb1,
               const float* __restrict__ bb2, const float* __restrict__ bb3,
               const float* __restrict__ cb1, const float* __restrict__ cb2,
               const float* __restrict__ cb3,
               const float* __restrict__ pos_emb, const float* __restrict__ action_emb,
               const float* __restrict__ active_emb, const float* __restrict__ street_emb,
               const float* __restrict__ numpl_emb, const float* __restrict__ blind_emb,
               const float* __restrict__ scalar_W, const float* __restrict__ scalar_b,
               float* __restrict__ out)
{
    extern __shared__ float smem[];
    float* blob = smem + OFF_BLOB;
    float* sW   = smem + OFF_SW;
    float* sB   = smem + OFF_SB;
    float* bias = smem + OFF_BIAS;
    float* A    = smem + OFF_A;      // stride 84
    float* Bb   = smem + OFF_B;      // stride 84
    float* C    = smem + OFF_C;      // stride 148
    float* D    = smem + OFF_A;      // stride 148 (overlays A+B)
    float* W    = smem + OFF_W;

    const int t = threadIdx.x;
    const size_t g0 = (size_t)blockIdx.x * TROWS;
    const float* st = state + g0 * 50;

    // ---- kick off h1 chunk0 staging immediately (overlaps all prologue work) ----
    stage_chunk<64, 64, 32>(W, g_wt);

    // ---- stage tables + biases ----
    for (int i = t; i < 40;  i += NTHREADS) blob[0   + i] = suit_emb[i];
    for (int i = t; i < 112; i += NTHREADS) blob[40  + i] = rank_emb[i];
    for (int i = t; i < 56;  i += NTHREADS) blob[152 + i] = pos_emb[i];
    for (int i = t; i < 96;  i += NTHREADS) blob[208 + i] = action_emb[i];
    for (int i = t; i < 16;  i += NTHREADS) blob[304 + i] = active_emb[i];
    for (int i = t; i < 40;  i += NTHREADS) blob[320 + i] = street_emb[i];
    for (int i = t; i < 56;  i += NTHREADS) blob[360 + i] = numpl_emb[i];
    for (int i = t; i < 16;  i += NTHREADS) blob[416 + i] = blind_emb[i];
    for (int i = t; i < 48;  i += NTHREADS) { sW[i] = scalar_W[i]; sB[i] = scalar_b[i]; }
    for (int i = t; i < 64;  i += NTHREADS) bias[0   + i] = hb1[i];
    for (int i = t; i < 64;  i += NTHREADS) bias[64  + i] = hb2[i];
    for (int i = t; i < 64;  i += NTHREADS) bias[128 + i] = hb3[i];
    for (int i = t; i < 80;  i += NTHREADS) bias[192 + i] = bb1[i];
    for (int i = t; i < 80;  i += NTHREADS) bias[272 + i] = bb2[i];
    for (int i = t; i < 80;  i += NTHREADS) bias[352 + i] = bb3[i];
    for (int i = t; i < 144; i += NTHREADS) bias[432 + i] = cb1[i];
    for (int i = t; i < 64;  i += NTHREADS) bias[576 + i] = cb2[i];
    for (int i = t; i < 64;  i += NTHREADS) bias[640 + i] = cb3[i];
    __syncthreads();

    const float4* blob4 = reinterpret_cast<const float4*>(blob);

    // ---- cheap output columns 64..311, vectorized: one (row, chunk) per iter ----
    for (int i = t; i < 31 * 64; i += NTHREADS) {
        int ch = i >> 6, r = i & 63;
        int kind = c_kind[ch], Ai = c_A[ch], Bc = c_B[ch];
        float4 va, vb;
        if (kind == 0) {
            int xi = (int)__ldg(st + r * 50 + Bc);
            va = blob4[(Ai >> 2) + xi * 2];
            vb = blob4[(Ai >> 2) + xi * 2 + 1];
        } else {
            float s = __ldg(st + r * 50 + Ai);
            float4 w0 = *reinterpret_cast<const float4*>(sW + Bc * 8);
            float4 w1 = *reinterpret_cast<const float4*>(sW + Bc * 8 + 4);
            float4 p0 = *reinterpret_cast<const float4*>(sB + Bc * 8);
            float4 p1 = *reinterpret_cast<const float4*>(sB + Bc * 8 + 4);
            va = make_float4(s * w0.x + p0.x, s * w0.y + p0.y, s * w0.z + p0.z, s * w0.w + p0.w);
            vb = make_float4(s * w1.x + p1.x, s * w1.y + p1.y, s * w1.z + p1.z, s * w1.w + p1.w);
        }
        float* op = out + (g0 + r) * 312 + 64 + ch * 8;
        *reinterpret_cast<float4*>(op)     = va;
        *reinterpret_cast<float4*>(op + 4) = vb;
    }

    // ---- gather hand input (4 cards x 16 feats) -> A, vectorized ----
    {
        int r = t >> 2, c = t & 3;  // 256 threads = 64 rows x 4 cards
        int s  = (int)__ldg(st + r * 50 + 2 * c + 1);
        int rk = (int)__ldg(st + r * 50 + 2 * c);
        float* ap = A + r * 84 + c * 16;
        *reinterpret_cast<float4*>(ap)      = blob4[s * 2];
        *reinterpret_cast<float4*>(ap + 4)  = blob4[s * 2 + 1];
        *reinterpret_cast<float4*>(ap + 8)  = blob4[10 + rk * 2];
        *reinterpret_cast<float4*>(ap + 12) = blob4[10 + rk * 2 + 1];
    }
    CPA_WAIT0();      // h1 chunk0 landed
    __syncthreads();  // A + weights visible

    layer4<64, 84, 64, 84,  0, 32, true , 0, 64, 64, 32>(A,  Bb, g_wt + 0,    bias + 0,   W, g_wt + 4096);
    layer4<64, 84, 64, 84,  0, 32, true , 0, 64, 64, 32>(Bb, A,  g_wt + 4096, bias + 64,  W, g_wt + 8192);
    layer4<64, 84, 64, 148, 0, 32, false, 0, 80, 80, 40>(A,  C,  g_wt + 8192, bias + 128, W, g_wt + 12288);

    // ---- gather board input (5 cards x 16 feats) -> A (WAR cleared by h3 barrier) ----
    for (int i = t; i < 64 * 8; i += NTHREADS) {
        int r = i >> 3, c = i & 7;
        if (c < 5) {
            int s  = (int)__ldg(st + r * 50 + 9 + 2 * c);
            int rk = (int)__ldg(st + r * 50 + 8 + 2 * c);
            float* ap = A + r * 84 + c * 16;
            *reinterpret_cast<float4*>(ap)      = blob4[s * 2];
            *reinterpret_cast<float4*>(ap + 4)  = blob4[s * 2 + 1];
            *reinterpret_cast<float4*>(ap + 8)  = blob4[10 + rk * 2];
            *reinterpret_cast<float4*>(ap + 12) = blob4[10 + rk * 2 + 1];
        }
    }
    __syncthreads();  // board gather visible (b1 weights already prefetched)

    layer4<80, 84, 80, 84,  0,  40, true , 0, 80, 80,  40>(A,  Bb, g_wt + 12288, bias + 192, W, g_wt + 18688);
    layer4<80, 84, 80, 84,  0,  40, true , 0, 80, 80,  40>(Bb, A,  g_wt + 18688, bias + 272, W, g_wt + 25088);
    layer4<80, 84, 80, 148, 64, 40, false, 0, 80, 144, 36>(A,  C,  g_wt + 25088, bias + 352, W, g_wt + 31488);

    // ---- combined MLP: C[144] -> D[144] -> C[0:64) -> out ----
    layer4<144, 148, 80, 148, 0,  36, true, 0, 64, 144, 36>(C, D, g_wt + 31488, bias + 432, W, g_wt + 43008);
    layer4<144, 148, 64, 148, 80, 36, true, 0, 64, 144, 48>(C, D, g_wt + 43008, bias + 512, W, g_wt + 52224);
    layer4<144, 148, 64, 148, 0,  48, true, 0, 64, 64,  32>(D, C, g_wt + 52224, bias + 576, W, g_wt + 61440);
    layer_final(C, g_wt + 61440, bias + 640, W, out, g0);
}

extern "C" void kernel_launch(void* const* d_in, const int* in_sizes, int n_in,
                              void* d_out, int out_size)
{
    (void)n_in; (void)out_size;
    cudaFuncSetAttribute(preproc_kernel, cudaFuncAttributeMaxDynamicSharedMemorySize, SMEM_BYTES);

    // one-time-per-graph weight transpose into g_wt
    prep_kernel<<<256, 256>>>(
        (const float*)d_in[3],  (const float*)d_in[5],  (const float*)d_in[7],
        (const float*)d_in[9],  (const float*)d_in[11], (const float*)d_in[13],
        (const float*)d_in[15], (const float*)d_in[17], (const float*)d_in[19]);

    const int nrows = in_sizes[0] / 50;     // 262144
    const int grid  = nrows / TROWS;        // 4096

    preproc_kernel<<<grid, NTHREADS, SMEM_BYTES>>>(
        (const float*)d_in[0],
        (const float*)d_in[1],  (const float*)d_in[2],
        (const float*)d_in[4],  (const float*)d_in[6],  (const float*)d_in[8],
        (const float*)d_in[10], (const float*)d_in[12], (const float*)d_in[14],
        (const float*)d_in[16], (const float*)d_in[18], (const float*)d_in[20],
        (const float*)d_in[21], (const float*)d_in[22],
        (const float*)d_in[23], (const float*)d_in[24],
        (const float*)d_in[25], (const float*)d_in[26],
        (const float*)d_in[27], (const float*)d_in[28],
        (float*)d_out);
}

// round 10
// speedup vs baseline: 1.5653x; 1.5653x over previous
#include <cuda_runtime.h>
#include <cstddef>

typedef unsigned long long ull;

#define NTHREADS 256
#define TROWS 64

// ======== transposed-weight global scratch: Wt[j][k] per layer ========
__device__ __align__(16) float g_wt[65536];
__constant__ int c_pre[10]  = {0,4096,8192,12288,18688,25088,31488,52224,61440,65536};
__constant__ int c_nin[9]   = {64,64,64,80,80,80,144,144,64};
__constant__ int c_nout[9]  = {64,64,64,80,80,80,144,64,64};

__global__ void prep_kernel(const float* w0,const float* w1,const float* w2,
                            const float* w3,const float* w4,const float* w5,
                            const float* w6,const float* w7,const float* w8)
{
    const float* W[9] = {w0,w1,w2,w3,w4,w5,w6,w7,w8};
    int i = blockIdx.x * blockDim.x + threadIdx.x;
    if (i >= 65536) return;
    int s = 0;
    while (i >= c_pre[s + 1]) s++;
    int l = i - c_pre[s];
    int nin = c_nin[s], nout = c_nout[s];
    int j = l / nin, k = l - j * nin;
    g_wt[i] = W[s][k * nout + j];
}

// ======== packed fp32x2 + cp.async helpers ========
__device__ __forceinline__ ull ffma2(ull a, ull b, ull c) {
    ull d; asm("fma.rn.f32x2 %0, %1, %2, %3;" : "=l"(d) : "l"(a), "l"(b), "l"(c)); return d;
}
__device__ __forceinline__ float2 u2f(ull a) {
    float2 f; asm("mov.b64 {%0, %1}, %2;" : "=f"(f.x), "=f"(f.y) : "l"(a)); return f;
}
__device__ __forceinline__ float lrelu(float v) { return v > 0.0f ? v : 0.01f * v; }
__device__ __forceinline__ void cpa16(float* dst, const float* src) {
    unsigned sa = (unsigned)__cvta_generic_to_shared(dst);
    asm volatile("cp.async.cg.shared.global [%0], [%1], 16;" :: "r"(sa), "l"(src));
}
#define CPA_COMMIT() asm volatile("cp.async.commit_group;" ::: "memory")
#define CPA_WAIT0()  asm volatile("cp.async.wait_group 0;"  ::: "memory")

// ======== epilogue chunk maps ========
__constant__ int c_kind[31] = {0,0,0,0,0,0,0,0,0,0,0,0,1,1,1,1,0,0,0,1,0,0,0,0,0,1,1,1,1,1,1};
__constant__ int c_A[31]    = {320,152,304,304,304,304,304,152,152,152,152,152,
                               40,41,42,43, 152,208,416, 39, 208,152,416,360,152,
                               44,45,46,47,48,49};
__constant__ int c_B[31]    = {18,20,22,23,24,25,26,27,28,29,30,31,
                               0,2,3,5, 35,36,37, 1, 32,33,34,19,38,
                               4,4,4,4,4,4};
// blob: suit@0(40) rank@40(112) pos@152(56) action@208(96) active@304(16)
//       street@320(40) numpl@360(56) blind@416(16)

// ======== shared layout (floats) ========
#define OFF_BLOB 0                   // 432
#define OFF_SW   432                 // 48
#define OFF_SB   480                 // 48
#define OFF_BIAS 528                 // 704 (ends 1232)
#define OFF_A    1232                // 64*84 = 5376 (stride 84)
#define OFF_B    6608                // 64*84 = 5376
#define OFF_C    11984               // 64*148 = 9472 (stride 148)
#define OFF_W    21456               // 2 slots * 3584
#define SLOTF    3584
#define SMEM_FLOATS 28624
#define SMEM_BYTES  (SMEM_FLOATS * 4)  // 114496 -> 2 CTAs/SM
// D (144-wide, stride 148) overlays A+B (10752 >= 9472)

// ======== dense (sub-)layer, cp.async double-buffered weights (R6 pipeline) ========
// Xs[row][k] stride SIN; Wtg = transposed weights [NJ][NIN] row-major;
// writes Ys[row][JOFF+j] stride SOUT. Warp w owns j-tile of NJ/8 cols.
template<int NIN, int SIN, int NJ, int SOUT, int JOFF, int KC, bool ACT>
__device__ __forceinline__ void layer(const float* __restrict__ Xs, float* __restrict__ Ys,
                                      const float* __restrict__ Wtg,
                                      const float* __restrict__ bsm,
                                      float* __restrict__ Wslots)
{
    const int t = threadIdx.x, L = t & 31, wid = t >> 5;
    constexpr int TILEJ = NJ / 8;
    constexpr int WS  = KC + 4;
    constexpr int NCH = NIN / KC;
    constexpr int PER = KC / 4;
    const int j0 = wid * TILEJ;

    ull acc[TILEJ][2];
    #pragma unroll
    for (int j = 0; j < TILEJ; j++) { acc[j][0] = 0ull; acc[j][1] = 0ull; }

    const float* x0 = Xs + L * SIN;
    const float* x1 = Xs + (L + 32) * SIN;

    // ---- stage chunk 0 ----
    {
        for (int i = t; i < NJ * PER; i += NTHREADS) {
            int j = i / PER, k4 = (i - j * PER) << 2;
            cpa16(Wslots + j * WS + k4, Wtg + j * NIN + k4);
        }
        CPA_COMMIT(); CPA_WAIT0();
    }
    __syncthreads();

    #pragma unroll
    for (int c = 0; c < NCH; c++) {
        if (c + 1 < NCH) {  // stage next chunk into other slot (overlapped)
            float* dst = Wslots + ((c + 1) & 1) * SLOTF;
            const float* src = Wtg + (c + 1) * KC;
            for (int i = t; i < NJ * PER; i += NTHREADS) {
                int j = i / PER, k4 = (i - j * PER) << 2;
                cpa16(dst + j * WS + k4, src + j * NIN + k4);
            }
            CPA_COMMIT();
        }
        // ---- compute chunk c ----
        {
            const float* Wt = Wslots + (c & 1) * SLOTF;
            const float* xk0 = x0 + c * KC;
            const float* xk1 = x1 + c * KC;
            const float* wr0 = Wt + j0 * WS;
            #pragma unroll 4
            for (int k = 0; k < KC; k += 4) {
                ulonglong2 xa = *reinterpret_cast<const ulonglong2*>(xk0 + k);
                ulonglong2 xb = *reinterpret_cast<const ulonglong2*>(xk1 + k);
                const float* wr = wr0 + k;
                #pragma unroll
                for (int j = 0; j < TILEJ; j++) {
                    ulonglong2 wv = *reinterpret_cast<const ulonglong2*>(wr + j * WS);
                    acc[j][0] = ffma2(xa.x, wv.x, acc[j][0]);
                    acc[j][0] = ffma2(xa.y, wv.y, acc[j][0]);
                    acc[j][1] = ffma2(xb.x, wv.x, acc[j][1]);
                    acc[j][1] = ffma2(xb.y, wv.y, acc[j][1]);
                }
            }
        }
        if (c + 1 < NCH) CPA_WAIT0();
        __syncthreads();
    }

    // ---- epilogue: horizontal add + bias (+act) ----
    #pragma unroll
    for (int j = 0; j < TILEJ; j += 2) {
        float b0 = bsm[j0 + j], b1 = bsm[j0 + j + 1];
        #pragma unroll
        for (int r = 0; r < 2; r++) {
            float2 s0 = u2f(acc[j][r]);
            float2 s1 = u2f(acc[j + 1][r]);
            float v0 = s0.x + s0.y + b0;
            float v1 = s1.x + s1.y + b1;
            if (ACT) { v0 = lrelu(v0); v1 = lrelu(v1); }
            *reinterpret_cast<float2*>(Ys + (L + 32 * r) * SOUT + JOFF + j0 + j) =
                make_float2(v0, v1);
        }
    }
}

// final 64->64 layer: no activation, writes out cols [0,64)
__device__ __forceinline__ void layer_final(const float* __restrict__ Xs,
                                            const float* __restrict__ Wtg,
                                            const float* __restrict__ bsm,
                                            float* __restrict__ Wslots,
                                            float* __restrict__ out, size_t g0)
{
    const int t = threadIdx.x, L = t & 31, wid = t >> 5;
    constexpr int KC = 32, WS = 36, NCH = 2, PER = 8;
    const int j0 = wid * 8;

    ull acc[8][2];
    #pragma unroll
    for (int j = 0; j < 8; j++) { acc[j][0] = 0ull; acc[j][1] = 0ull; }

    const float* x0 = Xs + L * 148;
    const float* x1 = Xs + (L + 32) * 148;

    {
        for (int i = t; i < 64 * PER; i += NTHREADS) {
            int j = i / PER, k4 = (i - j * PER) << 2;
            cpa16(Wslots + j * WS + k4, Wtg + j * 64 + k4);
        }
        CPA_COMMIT(); CPA_WAIT0();
    }
    __syncthreads();

    #pragma unroll
    for (int c = 0; c < NCH; c++) {
        if (c + 1 < NCH) {
            float* dst = Wslots + SLOTF;
            const float* src = Wtg + KC;
            for (int i = t; i < 64 * PER; i += NTHREADS) {
                int j = i / PER, k4 = (i - j * PER) << 2;
                cpa16(dst + j * WS + k4, src + j * 64 + k4);
            }
            CPA_COMMIT();
        }
        {
            const float* Wt = Wslots + (c & 1) * SLOTF;
            const float* xk0 = x0 + c * KC;
            const float* xk1 = x1 + c * KC;
            const float* wr0 = Wt + j0 * WS;
            #pragma unroll 4
            for (int k = 0; k < KC; k += 4) {
                ulonglong2 xa = *reinterpret_cast<const ulonglong2*>(xk0 + k);
                ulonglong2 xb = *reinterpret_cast<const ulonglong2*>(xk1 + k);
                const float* wr = wr0 + k;
                #pragma unroll
                for (int j = 0; j < 8; j++) {
                    ulonglong2 wv = *reinterpret_cast<const ulonglong2*>(wr + j * WS);
                    acc[j][0] = ffma2(xa.x, wv.x, acc[j][0]);
                    acc[j][0] = ffma2(xa.y, wv.y, acc[j][0]);
                    acc[j][1] = ffma2(xb.x, wv.x, acc[j][1]);
                    acc[j][1] = ffma2(xb.y, wv.y, acc[j][1]);
                }
            }
        }
        if (c + 1 < NCH) CPA_WAIT0();
        __syncthreads();
    }

    #pragma unroll
    for (int r = 0; r < 2; r++) {
        float v[8];
        #pragma unroll
        for (int j = 0; j < 8; j++) {
            float2 s = u2f(acc[j][r]);
            v[j] = s.x + s.y + bsm[j0 + j];
        }
        float* op = out + (g0 + L + 32 * r) * 312 + j0;
        *reinterpret_cast<float4*>(op)     = make_float4(v[0], v[1], v[2], v[3]);
        *reinterpret_cast<float4*>(op + 4) = make_float4(v[4], v[5], v[6], v[7]);
    }
}

__global__ void __launch_bounds__(NTHREADS, 2)
preproc_kernel(const float* __restrict__ state,
               const float* __restrict__ suit_emb, const float* __restrict__ rank_emb,
               const float* __restrict__ hb1, const float* __restrict__ hb2,
               const float* __restrict__ hb3, const float* __restrict__ bb1,
               const float* __restrict__ bb2, const float* __restrict__ bb3,
               const float* __restrict__ cb1, const float* __restrict__ cb2,
               const float* __restrict__ cb3,
               const float* __restrict__ pos_emb, const float* __restrict__ action_emb,
               const float* __restrict__ active_emb, const float* __restrict__ street_emb,
               const float* __restrict__ numpl_emb, const float* __restrict__ blind_emb,
               const float* __restrict__ scalar_W, const float* __restrict__ scalar_b,
               float* __restrict__ out)
{
    extern __shared__ float smem[];
    float* blob = smem + OFF_BLOB;
    float* sW   = smem + OFF_SW;
    float* sB   = smem + OFF_SB;
    float* bias = smem + OFF_BIAS;
    float* A    = smem + OFF_A;      // stride 84
    float* Bb   = smem + OFF_B;      // stride 84
    float* C    = smem + OFF_C;      // stride 148
    float* D    = smem + OFF_A;      // stride 148 (overlays A+B)
    float* W    = smem + OFF_W;

    const int t = threadIdx.x;
    const size_t g0 = (size_t)blockIdx.x * TROWS;
    const float* st = state + g0 * 50;

    // ---- stage tables + biases ----
    for (int i = t; i < 40;  i += NTHREADS) blob[0   + i] = suit_emb[i];
    for (int i = t; i < 112; i += NTHREADS) blob[40  + i] = rank_emb[i];
    for (int i = t; i < 56;  i += NTHREADS) blob[152 + i] = pos_emb[i];
    for (int i = t; i < 96;  i += NTHREADS) blob[208 + i] = action_emb[i];
    for (int i = t; i < 16;  i += NTHREADS) blob[304 + i] = active_emb[i];
    for (int i = t; i < 40;  i += NTHREADS) blob[320 + i] = street_emb[i];
    for (int i = t; i < 56;  i += NTHREADS) blob[360 + i] = numpl_emb[i];
    for (int i = t; i < 16;  i += NTHREADS) blob[416 + i] = blind_emb[i];
    for (int i = t; i < 48;  i += NTHREADS) { sW[i] = scalar_W[i]; sB[i] = scalar_b[i]; }
    for (int i = t; i < 64;  i += NTHREADS) bias[0   + i] = hb1[i];
    for (int i = t; i < 64;  i += NTHREADS) bias[64  + i] = hb2[i];
    for (int i = t; i < 64;  i += NTHREADS) bias[128 + i] = hb3[i];
    for (int i = t; i < 80;  i += NTHREADS) bias[192 + i] = bb1[i];
    for (int i = t; i < 80;  i += NTHREADS) bias[272 + i] = bb2[i];
    for (int i = t; i < 80;  i += NTHREADS) bias[352 + i] = bb3[i];
    for (int i = t; i < 144; i += NTHREADS) bias[432 + i] = cb1[i];
    for (int i = t; i < 64;  i += NTHREADS) bias[576 + i] = cb2[i];
    for (int i = t; i < 64;  i += NTHREADS) bias[640 + i] = cb3[i];
    __syncthreads();

    const float4* blob4 = reinterpret_cast<const float4*>(blob);

    // ---- cheap output columns 64..311: coalesced float4 stores ----
    // thread i -> row r = i/62, quad q = i%62; lanes hit consecutive out addresses
    for (int i = t; i < 64 * 62; i += NTHREADS) {
        int r = i / 62, q = i - r * 62;
        int ch = q >> 1, half = q & 1;
        int kind = c_kind[ch], Ai = c_A[ch], Bc = c_B[ch];
        float4 v;
        if (kind == 0) {
            int xi = (int)__ldg(st + r * 50 + Bc);
            v = blob4[(Ai >> 2) + xi * 2 + half];
        } else {
            float s = __ldg(st + r * 50 + Ai);
            float4 w = *reinterpret_cast<const float4*>(sW + Bc * 8 + half * 4);
            float4 p = *reinterpret_cast<const float4*>(sB + Bc * 8 + half * 4);
            v = make_float4(s * w.x + p.x, s * w.y + p.y, s * w.z + p.z, s * w.w + p.w);
        }
        *reinterpret_cast<float4*>(out + (g0 + r) * 312 + 64 + q * 4) = v;
    }

    // ---- gather hand input (4 cards x 16 feats) -> A, vectorized ----
    {
        int r = t >> 2, c = t & 3;  // 256 threads = 64 rows x 4 cards
        int s  = (int)__ldg(st + r * 50 + 2 * c + 1);
        int rk = (int)__ldg(st + r * 50 + 2 * c);
        float* ap = A + r * 84 + c * 16;
        *reinterpret_cast<float4*>(ap)      = blob4[s * 2];
        *reinterpret_cast<float4*>(ap + 4)  = blob4[s * 2 + 1];
        *reinterpret_cast<float4*>(ap + 8)  = blob4[10 + rk * 2];
        *reinterpret_cast<float4*>(ap + 12) = blob4[10 + rk * 2 + 1];
    }
    // (h1's chunk-0 stage barrier establishes visibility of A)

    layer<64, 84, 64, 84,  0,  32, true >(A,  Bb, g_wt + 0,     bias + 0,   W);
    layer<64, 84, 64, 84,  0,  32, true >(Bb, A,  g_wt + 4096,  bias + 64,  W);
    layer<64, 84, 64, 148, 0,  32, false>(A,  C,  g_wt + 8192,  bias + 128, W);

    __syncthreads();  // h3 done reading A before board gather overwrites

    // ---- gather board input (5 cards x 16 feats) -> A, vectorized ----
    for (int i = t; i < 64 * 8; i += NTHREADS) {
        int r = i >> 3, c = i & 7;
        if (c < 5) {
            int s  = (int)__ldg(st + r * 50 + 9 + 2 * c);
            int rk = (int)__ldg(st + r * 50 + 8 + 2 * c);
            float* ap = A + r * 84 + c * 16;
            *reinterpret_cast<float4*>(ap)      = blob4[s * 2];
            *reinterpret_cast<float4*>(ap + 4)  = blob4[s * 2 + 1];
            *reinterpret_cast<float4*>(ap + 8)  = blob4[10 + rk * 2];
            *reinterpret_cast<float4*>(ap + 12) = blob4[10 + rk * 2 + 1];
        }
    }

    layer<80, 84, 80, 84,  0,  40, true >(A,  Bb, g_wt + 12288, bias + 192, W);
    layer<80, 84, 80, 84,  0,  40, true >(Bb, A,  g_wt + 18688, bias + 272, W);
    layer<80, 84, 80, 148, 64, 40, false>(A,  C,  g_wt + 25088, bias + 352, W);

    // ---- combined MLP: C[144] -> D[144] -> C[0:64) -> out ----
    layer<144, 148, 80, 148, 0,  36, true>(C, D, g_wt + 31488,            bias + 432,      W);
    layer<144, 148, 64, 148, 80, 36, true>(C, D, g_wt + 31488 + 80 * 144, bias + 432 + 80, W);
    layer<144, 148, 64, 148, 0,  48, true>(D, C, g_wt + 52224,            bias + 576,      W);
    layer_final(C, g_wt + 61440, bias + 640, W, out, g0);
}

extern "C" void kernel_launch(void* const* d_in, const int* in_sizes, int n_in,
                              void* d_out, int out_size)
{
    (void)n_in; (void)out_size;
    cudaFuncSetAttribute(preproc_kernel, cudaFuncAttributeMaxDynamicSharedMemorySize, SMEM_BYTES);

    // one-time-per-graph weight transpose into g_wt
    prep_kernel<<<256, 256>>>(
        (const float*)d_in[3],  (const float*)d_in[5],  (const float*)d_in[7],
        (const float*)d_in[9],  (const float*)d_in[11], (const float*)d_in[13],
        (const float*)d_in[15], (const float*)d_in[17], (const float*)d_in[19]);

    const int nrows = in_sizes[0] / 50;     // 262144
    const int grid  = nrows / TROWS;        // 4096

    preproc_kernel<<<grid, NTHREADS, SMEM_BYTES>>>(
        (const float*)d_in[0],
        (const float*)d_in[1],  (const float*)d_in[2],
        (const float*)d_in[4],  (const float*)d_in[6],  (const float*)d_in[8],
        (const float*)d_in[10], (const float*)d_in[12], (const float*)d_in[14],
        (const float*)d_in[16], (const float*)d_in[18], (const float*)d_in[20],
        (const float*)d_in[21], (const float*)d_in[22],
        (const float*)d_in[23], (const float*)d_in[24],
        (const float*)d_in[25], (const float*)d_in[26],
        (const float*)d_in[27], (const float*)d_in[28],
        (float*)d_out);
}